// round 12
// baseline (speedup 1.0000x reference)
#include <cuda_runtime.h>
#include <cstdint>

// Problem constants (fixed by the dataset)
#define BTOT   4096      // 4*1024 rows
#define DIN    2048
#define NBLK   4
#define LBLK   512       // LIN = LOUT = 512 per block
#define RR     8
// core_i layout: [r][o][x][s] strides (2097152, 4096, 8, 1), 16,777,216 floats each

// ---------------- scratch (__device__ globals; no allocation) ----------------
__device__ float g_part[4*8*8*4096];        // partial Ghat sums  (4 MB)
__device__ float g_ghat[4*8*4096];          // Ghat[i][r][x*8+s]  (512 KB)
__device__ float g_env [BTOT*4*64];         // env[b][i][r*8+s]   (4 MB)
__device__ float g_xT  [4*LBLK*BTOT];       // xT[d][b], d=i*512+x (32 MB)

// ---------------- kernel 1a: partial reduction of G over o ----------------
__global__ void ghat_part_kernel(const float* __restrict__ c0, const float* __restrict__ c1,
                                 const float* __restrict__ c2, const float* __restrict__ c3)
{
    int oc = blockIdx.x;            // 0..7  (64 o's each)
    int r  = blockIdx.y;            // 0..7
    int i  = blockIdx.z;            // 0..3
    const float* core = (i==0)?c0:(i==1)?c1:(i==2)?c2:c3;
    const float* base = core + (size_t)r*2097152 + (size_t)oc*64*4096;
    int tid = threadIdx.x;          // 256 threads
    float acc[16];
#pragma unroll
    for (int j=0;j<16;j++) acc[j] = 0.f;
    for (int o=0;o<64;o++){
        const float* row = base + (size_t)o*4096;
#pragma unroll
        for (int j=0;j<16;j++) acc[j] += row[tid + j*256];
    }
    float* dst = g_part + (size_t)((i*8+r)*8 + oc)*4096;
#pragma unroll
    for (int j=0;j<16;j++) dst[tid + j*256] = acc[j];
}

// ---------------- kernel 1b: final deterministic sum ----------------
__global__ void ghat_sum_kernel()
{
    int r = blockIdx.x;             // 0..7
    int i = blockIdx.y;             // 0..3
    int tid = threadIdx.x;          // 256
    const float* src = g_part + (size_t)((i*8+r)*8)*4096;
    float* dst = g_ghat + (size_t)(i*8+r)*4096;
#pragma unroll
    for (int j=0;j<16;j++){
        int xs = tid + j*256;
        float s = 0.f;
#pragma unroll
        for (int oc=0;oc<8;oc++) s += src[(size_t)oc*4096 + xs];
        dst[xs] = s;
    }
}

// ---------------- kernel 2: transpose inputs -> xT[d][b] ----------------
__global__ void transpose_kernel(const float* __restrict__ in)
{
    __shared__ float tile[32][33];
    int d0 = blockIdx.x*32;         // feature dim (0..2047)
    int b0 = blockIdx.y*32;         // batch dim   (0..4095)
    int tx = threadIdx.x, ty = threadIdx.y;   // 32 x 8
#pragma unroll
    for (int j=0;j<32;j+=8)
        tile[ty+j][tx] = in[(size_t)(b0+ty+j)*DIN + d0 + tx];
    __syncthreads();
#pragma unroll
    for (int j=0;j<32;j+=8)
        g_xT[(size_t)(d0+ty+j)*BTOT + b0 + tx] = tile[tx][ty+j];
}

// ---------------- kernel 3: S (per-b ring matrices) + env chains ----------------
__global__ void s_env_kernel(const float* __restrict__ in)
{
    __shared__ float xrow[DIN];
    __shared__ float Ssm[4][64];
    __shared__ float P2[64], P3[64], Q1[64], Q0[64];
    int b = blockIdx.x;
    int tid = threadIdx.x;          // 256
#pragma unroll
    for (int j=0;j<8;j++) xrow[tid + j*256] = in[(size_t)b*DIN + tid + j*256];
    __syncthreads();

    // each thread: one (i, r, s) dot product of length 512
    {
        int i = tid>>6, rs = tid&63, r = rs>>3, s = rs&7;
        const float* gp = g_ghat + (size_t)(i*8+r)*4096 + s;   // + x*8
        const float* xp = xrow + i*512;
        float acc = 0.f;
#pragma unroll 8
        for (int x=0;x<512;x++) acc += xp[x]*gp[x*8];
        Ssm[i][rs] = acc;
    }
    __syncthreads();

    // 8x8 chain: P2=S0@S1, Q1=S2@S3
    if (tid < 64){
        int rr = tid>>3, cc = tid&7;
        float p2=0.f, q1=0.f;
#pragma unroll
        for (int p=0;p<8;p++){
            p2 += Ssm[0][rr*8+p]*Ssm[1][p*8+cc];
            q1 += Ssm[2][rr*8+p]*Ssm[3][p*8+cc];
        }
        P2[tid]=p2; Q1[tid]=q1;
    }
    __syncthreads();
    // P3=P2@S2, Q0=S1@Q1
    if (tid < 64){
        int rr = tid>>3, cc = tid&7;
        float p3=0.f, q0=0.f;
#pragma unroll
        for (int p=0;p<8;p++){
            p3 += P2[rr*8+p]*Ssm[2][p*8+cc];
            q0 += Ssm[1][rr*8+p]*Q1[p*8+cc];
        }
        P3[tid]=p3; Q0[tid]=q0;
    }
    __syncthreads();
    // env_i[r][s] = sum_p Q_i[s][p] * P_i[p][r]
    if (tid < 64){
        int rr = tid>>3, ss = tid&7;
        float e0 = Q0[ss*8+rr];                 // P0 = I
        float e1 = 0.f, e2 = 0.f;
#pragma unroll
        for (int p=0;p<8;p++){
            e1 += Q1[ss*8+p]*Ssm[0][p*8+rr];    // P1 = S0
            e2 += Ssm[3][ss*8+p]*P2[p*8+rr];    // Q2 = S3, P2 = S0S1
        }
        float e3 = P3[ss*8+rr];                 // Q3 = I
        float* eb = g_env + (size_t)b*256;      // [b][i][64]
        eb[       tid] = e0;
        eb[ 64 +  tid] = e1;
        eb[128 +  tid] = e2;
        eb[192 +  tid] = e3;
    }
}

// ---------------- kernel 4: the big GEMM (on-the-fly A = env (x) x) ----------------
// Tile: BM=128 (b), BN=128 (o), BK=32, 256 threads, thread tile 8m x 8n (f32x2 over n-pairs)
// smem carve: As_dup float2[32][128] (32768 B) | Bs float[32][130] (16640 B) | env float[128][65] (33280 B)
// Bs pitch MUST be even: the compute loop does 8-byte loads at Bs[kk*pitch + 2*tx],
// so odd pitch (129) produced addresses == 4 mod 8 for odd kk -> misaligned trap.
#define BS_PITCH 130
#define GEMM_SMEM (32768 + 32*BS_PITCH*4 + 33280)

__device__ __forceinline__ void fma2(unsigned long long& d, unsigned long long a, unsigned long long b){
    asm("fma.rn.f32x2 %0, %1, %2, %0;" : "+l"(d) : "l"(a), "l"(b));
}

__global__ __launch_bounds__(256, 2) void gemm_kernel(
    const float* __restrict__ c0, const float* __restrict__ c1,
    const float* __restrict__ c2, const float* __restrict__ c3,
    const float* __restrict__ bias, float* __restrict__ out)
{
    extern __shared__ char smraw[];
    float2* As    = (float2*)(smraw);                            // [32][128] duplicated pairs (v,v)
    float*  Bs    = (float*) (smraw + 32768);                    // [32][BS_PITCH]
    float*  env_s = (float*) (smraw + 32768 + 32*BS_PITCH*4);    // [128][65]
    const unsigned long long* Asu = (const unsigned long long*)As;

    int tid = threadIdx.x;
    int i   = blockIdx.z;
    const float* core = (i==0)?c0:(i==1)?c1:(i==2)?c2:c3;
    int bRow0 = blockIdx.x * 128;
    int n0    = blockIdx.y * 128;

    // stage env for this M-tile: env_s[m][rs], pitch 65 (conflict-free)
#pragma unroll
    for (int v=0; v<32; v++){
        int idx = v*256 + tid;
        int m = idx>>6, rs = idx&63;
        env_s[m*65 + rs] = g_env[(size_t)(bRow0+m)*256 + i*64 + rs];
    }
    __syncthreads();

    unsigned long long acc[8][4];
#pragma unroll
    for (int jm=0;jm<8;jm++)
#pragma unroll
        for (int jn=0;jn<4;jn++) acc[jm][jn] = 0ull;

    int tx = tid & 15;      // n group
    int ty = tid >> 4;      // m group

    for (int kt=0; kt<1024; kt++){
        int r  = kt >> 7;               // (kt*32)/4096
        int x0 = (kt*4) & 511;          // ((kt*32)/8) % 512

        // load B tile: Bs[kk][n] = core[r][n0+n][x0*8 + kk]
        const float* bsrc = core + (size_t)r*2097152 + (size_t)n0*4096 + x0*8;
#pragma unroll
        for (int v=0; v<4; v++){
            int idx = v*256 + tid;
            int n = idx>>3, q = idx&7;
            float4 t = *(const float4*)(bsrc + (size_t)n*4096 + q*4);
            int kk = q*4;
            Bs[(kk  )*BS_PITCH + n] = t.x;
            Bs[(kk+1)*BS_PITCH + n] = t.y;
            Bs[(kk+2)*BS_PITCH + n] = t.z;
            Bs[(kk+3)*BS_PITCH + n] = t.w;
        }
        // generate A tile: As[kk][m] = dup( env[m][r*8 + (kk&7)] * x[m][x0 + (kk>>3)] )
        const float* xbase = g_xT + ((size_t)i*512 + x0)*BTOT + bRow0;
#pragma unroll
        for (int v=0; v<16; v++){
            int idx = v*256 + tid;
            int m = idx & 127, kk = idx >> 7;
            float xv  = xbase[(kk>>3)*BTOT + m];
            float val = env_s[m*65 + r*8 + (kk&7)] * xv;
            As[kk*128 + m] = make_float2(val, val);
        }
        __syncthreads();

#pragma unroll 8
        for (int kk=0; kk<32; kk++){
            unsigned long long a[8], bb[4];
#pragma unroll
            for (int jm=0;jm<8;jm++) a[jm] = Asu[kk*128 + ty + 16*jm];
#pragma unroll
            for (int jn=0;jn<4;jn++) bb[jn] = *(const unsigned long long*)&Bs[kk*BS_PITCH + tx*2 + 32*jn];
#pragma unroll
            for (int jm=0;jm<8;jm++)
#pragma unroll
                for (int jn=0;jn<4;jn++) fma2(acc[jm][jn], a[jm], bb[jn]);
        }
        __syncthreads();
    }

    // epilogue: unpack, add bias, store
#pragma unroll
    for (int jm=0;jm<8;jm++){
        int m = ty + 16*jm;
        size_t rowoff = (size_t)(bRow0+m)*DIN + i*512 + n0;
#pragma unroll
        for (int jn=0;jn<4;jn++){
            int n = tx*2 + 32*jn;
            float2 c;
            asm("mov.b64 {%0, %1}, %2;" : "=f"(c.x), "=f"(c.y) : "l"(acc[jm][jn]));
            c.x += bias[i*512 + n0 + n];
            c.y += bias[i*512 + n0 + n + 1];
            *(float2*)&out[rowoff + n] = c;
        }
    }
}

// ---------------- launch ----------------
extern "C" void kernel_launch(void* const* d_in, const int* in_sizes, int n_in,
                              void* d_out, int out_size)
{
    const float* inp  = (const float*)d_in[0];
    const float* c0   = (const float*)d_in[1];
    const float* c1   = (const float*)d_in[2];
    const float* c2   = (const float*)d_in[3];
    const float* c3   = (const float*)d_in[4];
    const float* bias = (const float*)d_in[5];
    float* out = (float*)d_out;

    cudaFuncSetAttribute(gemm_kernel, cudaFuncAttributeMaxDynamicSharedMemorySize, GEMM_SMEM);

    ghat_part_kernel<<<dim3(8,8,4), 256>>>(c0, c1, c2, c3);
    ghat_sum_kernel <<<dim3(8,4),   256>>>();
    transpose_kernel<<<dim3(64,128), dim3(32,8)>>>(inp);
    s_env_kernel    <<<dim3(4096),  256>>>(inp);
    gemm_kernel     <<<dim3(32,4,4), 256, GEMM_SMEM>>>(c0, c1, c2, c3, bias, out);
}

// round 14
// speedup vs baseline: 1.0098x; 1.0098x over previous
#include <cuda_runtime.h>
#include <cstdint>

// Problem constants (fixed by the dataset)
#define BTOT   4096      // 4*1024 rows
#define DIN    2048
#define NBLK   4
#define LBLK   512       // LIN = LOUT = 512 per block
#define RR     8
// core_i layout: [r][o][x][s] strides (2097152, 4096, 8, 1), 16,777,216 floats each

// ---------------- scratch (__device__ globals; no allocation) ----------------
__device__ float g_part[4*8*8*4096];        // partial Ghat sums  (4 MB)
__device__ float g_ghat[4*8*4096];          // Ghat[i][r][x*8+s]  (512 KB)
__device__ float g_env [BTOT*4*64];         // env[b][i][r*8+s]   (4 MB)
__device__ float g_xT  [4*LBLK*BTOT];       // xT[d][b], d=i*512+x (32 MB)

// ---------------- kernel 1a: partial reduction of G over o ----------------
__global__ void ghat_part_kernel(const float* __restrict__ c0, const float* __restrict__ c1,
                                 const float* __restrict__ c2, const float* __restrict__ c3)
{
    int oc = blockIdx.x;            // 0..7  (64 o's each)
    int r  = blockIdx.y;            // 0..7
    int i  = blockIdx.z;            // 0..3
    const float* core = (i==0)?c0:(i==1)?c1:(i==2)?c2:c3;
    const float* base = core + (size_t)r*2097152 + (size_t)oc*64*4096;
    int tid = threadIdx.x;          // 256 threads
    float acc[16];
#pragma unroll
    for (int j=0;j<16;j++) acc[j] = 0.f;
    for (int o=0;o<64;o++){
        const float* row = base + (size_t)o*4096;
#pragma unroll
        for (int j=0;j<16;j++) acc[j] += row[tid + j*256];
    }
    float* dst = g_part + (size_t)((i*8+r)*8 + oc)*4096;
#pragma unroll
    for (int j=0;j<16;j++) dst[tid + j*256] = acc[j];
}

// ---------------- kernel 1b: final deterministic sum ----------------
__global__ void ghat_sum_kernel()
{
    int r = blockIdx.x;             // 0..7
    int i = blockIdx.y;             // 0..3
    int tid = threadIdx.x;          // 256
    const float* src = g_part + (size_t)((i*8+r)*8)*4096;
    float* dst = g_ghat + (size_t)(i*8+r)*4096;
#pragma unroll
    for (int j=0;j<16;j++){
        int xs = tid + j*256;
        float s = 0.f;
#pragma unroll
        for (int oc=0;oc<8;oc++) s += src[(size_t)oc*4096 + xs];
        dst[xs] = s;
    }
}

// ---------------- kernel 2: transpose inputs -> xT[d][b] ----------------
__global__ void transpose_kernel(const float* __restrict__ in)
{
    __shared__ float tile[32][33];
    int d0 = blockIdx.x*32;         // feature dim (0..2047)
    int b0 = blockIdx.y*32;         // batch dim   (0..4095)
    int tx = threadIdx.x, ty = threadIdx.y;   // 32 x 8
#pragma unroll
    for (int j=0;j<32;j+=8)
        tile[ty+j][tx] = in[(size_t)(b0+ty+j)*DIN + d0 + tx];
    __syncthreads();
#pragma unroll
    for (int j=0;j<32;j+=8)
        g_xT[(size_t)(d0+ty+j)*BTOT + b0 + tx] = tile[tx][ty+j];
}

// ---------------- kernel 3: S (per-b ring matrices) + env chains ----------------
__global__ void s_env_kernel(const float* __restrict__ in)
{
    __shared__ float xrow[DIN];
    __shared__ float Ssm[4][64];
    __shared__ float P2[64], P3[64], Q1[64], Q0[64];
    int b = blockIdx.x;
    int tid = threadIdx.x;          // 256
#pragma unroll
    for (int j=0;j<8;j++) xrow[tid + j*256] = in[(size_t)b*DIN + tid + j*256];
    __syncthreads();

    // each thread: one (i, r, s) dot product of length 512
    {
        int i = tid>>6, rs = tid&63, r = rs>>3, s = rs&7;
        const float* gp = g_ghat + (size_t)(i*8+r)*4096 + s;   // + x*8
        const float* xp = xrow + i*512;
        float acc = 0.f;
#pragma unroll 8
        for (int x=0;x<512;x++) acc += xp[x]*gp[x*8];
        Ssm[i][rs] = acc;
    }
    __syncthreads();

    // 8x8 chain: P2=S0@S1, Q1=S2@S3
    if (tid < 64){
        int rr = tid>>3, cc = tid&7;
        float p2=0.f, q1=0.f;
#pragma unroll
        for (int p=0;p<8;p++){
            p2 += Ssm[0][rr*8+p]*Ssm[1][p*8+cc];
            q1 += Ssm[2][rr*8+p]*Ssm[3][p*8+cc];
        }
        P2[tid]=p2; Q1[tid]=q1;
    }
    __syncthreads();
    // P3=P2@S2, Q0=S1@Q1
    if (tid < 64){
        int rr = tid>>3, cc = tid&7;
        float p3=0.f, q0=0.f;
#pragma unroll
        for (int p=0;p<8;p++){
            p3 += P2[rr*8+p]*Ssm[2][p*8+cc];
            q0 += Ssm[1][rr*8+p]*Q1[p*8+cc];
        }
        P3[tid]=p3; Q0[tid]=q0;
    }
    __syncthreads();
    // env_i[r][s] = sum_p Q_i[s][p] * P_i[p][r]
    if (tid < 64){
        int rr = tid>>3, ss = tid&7;
        float e0 = Q0[ss*8+rr];                 // P0 = I
        float e1 = 0.f, e2 = 0.f;
#pragma unroll
        for (int p=0;p<8;p++){
            e1 += Q1[ss*8+p]*Ssm[0][p*8+rr];    // P1 = S0
            e2 += Ssm[3][ss*8+p]*P2[p*8+rr];    // Q2 = S3, P2 = S0S1
        }
        float e3 = P3[ss*8+rr];                 // Q3 = I
        float* eb = g_env + (size_t)b*256;      // [b][i][64]
        eb[       tid] = e0;
        eb[ 64 +  tid] = e1;
        eb[128 +  tid] = e2;
        eb[192 +  tid] = e3;
    }
}

// ---------------- kernel 4: the big GEMM (on-the-fly A = env (x) x) ----------------
// Tile: BM=128 (b), BN=128 (o), BK=32, 256 threads, thread tile 8m x 8n (f32x2 over n-pairs)
// smem carve: As_dup float2[32][128] (32768 B) | Bs float[32][130] (16640 B) | env float[128][65] (33280 B)
// Bs pitch MUST be even: the compute loop does 8-byte loads at Bs[kk*pitch + 2*tx],
// so odd pitch (129) produced addresses == 4 mod 8 for odd kk -> misaligned trap.
#define BS_PITCH 130
#define GEMM_SMEM (32768 + 32*BS_PITCH*4 + 33280)

__device__ __forceinline__ void fma2(unsigned long long& d, unsigned long long a, unsigned long long b){
    asm("fma.rn.f32x2 %0, %1, %2, %0;" : "+l"(d) : "l"(a), "l"(b));
}

__global__ __launch_bounds__(256, 2) void gemm_kernel(
    const float* __restrict__ c0, const float* __restrict__ c1,
    const float* __restrict__ c2, const float* __restrict__ c3,
    const float* __restrict__ bias, float* __restrict__ out)
{
    extern __shared__ char smraw[];
    float2* As    = (float2*)(smraw);                            // [32][128] duplicated pairs (v,v)
    float*  Bs    = (float*) (smraw + 32768);                    // [32][BS_PITCH]
    float*  env_s = (float*) (smraw + 32768 + 32*BS_PITCH*4);    // [128][65]
    const unsigned long long* Asu = (const unsigned long long*)As;

    int tid = threadIdx.x;
    int i   = blockIdx.z;
    const float* core = (i==0)?c0:(i==1)?c1:(i==2)?c2:c3;
    int bRow0 = blockIdx.x * 128;
    int n0    = blockIdx.y * 128;

    // stage env for this M-tile: env_s[m][rs], pitch 65 (conflict-free)
#pragma unroll
    for (int v=0; v<32; v++){
        int idx = v*256 + tid;
        int m = idx>>6, rs = idx&63;
        env_s[m*65 + rs] = g_env[(size_t)(bRow0+m)*256 + i*64 + rs];
    }
    __syncthreads();

    unsigned long long acc[8][4];
#pragma unroll
    for (int jm=0;jm<8;jm++)
#pragma unroll
        for (int jn=0;jn<4;jn++) acc[jm][jn] = 0ull;

    int tx = tid & 15;      // n group
    int ty = tid >> 4;      // m group

    for (int kt=0; kt<1024; kt++){
        int r  = kt >> 7;               // (kt*32)/4096
        int x0 = (kt*4) & 511;          // ((kt*32)/8) % 512

        // load B tile: Bs[kk][n] = core[r][n0+n][x0*8 + kk]
        const float* bsrc = core + (size_t)r*2097152 + (size_t)n0*4096 + x0*8;
#pragma unroll
        for (int v=0; v<4; v++){
            int idx = v*256 + tid;
            int n = idx>>3, q = idx&7;
            float4 t = *(const float4*)(bsrc + (size_t)n*4096 + q*4);
            int kk = q*4;
            Bs[(kk  )*BS_PITCH + n] = t.x;
            Bs[(kk+1)*BS_PITCH + n] = t.y;
            Bs[(kk+2)*BS_PITCH + n] = t.z;
            Bs[(kk+3)*BS_PITCH + n] = t.w;
        }
        // generate A tile: As[kk][m] = dup( env[m][r*8 + (kk&7)] * x[m][x0 + (kk>>3)] )
        const float* xbase = g_xT + ((size_t)i*512 + x0)*BTOT + bRow0;
#pragma unroll
        for (int v=0; v<16; v++){
            int idx = v*256 + tid;
            int m = idx & 127, kk = idx >> 7;
            float xv  = xbase[(kk>>3)*BTOT + m];
            float val = env_s[m*65 + r*8 + (kk&7)] * xv;
            As[kk*128 + m] = make_float2(val, val);
        }
        __syncthreads();

#pragma unroll 8
        for (int kk=0; kk<32; kk++){
            unsigned long long a[8], bb[4];
#pragma unroll
            for (int jm=0;jm<8;jm++) a[jm] = Asu[kk*128 + ty + 16*jm];
#pragma unroll
            for (int jn=0;jn<4;jn++) bb[jn] = *(const unsigned long long*)&Bs[kk*BS_PITCH + tx*2 + 32*jn];
#pragma unroll
            for (int jm=0;jm<8;jm++)
#pragma unroll
                for (int jn=0;jn<4;jn++) fma2(acc[jm][jn], a[jm], bb[jn]);
        }
        __syncthreads();
    }

    // epilogue: unpack, add bias, store
#pragma unroll
    for (int jm=0;jm<8;jm++){
        int m = ty + 16*jm;
        size_t rowoff = (size_t)(bRow0+m)*DIN + i*512 + n0;
#pragma unroll
        for (int jn=0;jn<4;jn++){
            int n = tx*2 + 32*jn;
            float2 c;
            asm("mov.b64 {%0, %1}, %2;" : "=f"(c.x), "=f"(c.y) : "l"(acc[jm][jn]));
            c.x += bias[i*512 + n0 + n];
            c.y += bias[i*512 + n0 + n + 1];
            *(float2*)&out[rowoff + n] = c;
        }
    }
}

// ---------------- launch ----------------
extern "C" void kernel_launch(void* const* d_in, const int* in_sizes, int n_in,
                              void* d_out, int out_size)
{
    const float* inp  = (const float*)d_in[0];
    const float* c0   = (const float*)d_in[1];
    const float* c1   = (const float*)d_in[2];
    const float* c2   = (const float*)d_in[3];
    const float* c3   = (const float*)d_in[4];
    const float* bias = (const float*)d_in[5];
    float* out = (float*)d_out;

    cudaFuncSetAttribute(gemm_kernel, cudaFuncAttributeMaxDynamicSharedMemorySize, GEMM_SMEM);

    ghat_part_kernel<<<dim3(8,8,4), 256>>>(c0, c1, c2, c3);
    ghat_sum_kernel <<<dim3(8,4),   256>>>();
    transpose_kernel<<<dim3(64,128), dim3(32,8)>>>(inp);
    s_env_kernel    <<<dim3(4096),  256>>>(inp);
    gemm_kernel     <<<dim3(32,4,4), 256, GEMM_SMEM>>>(c0, c1, c2, c3, bias, out);
}